// round 1
// baseline (speedup 1.0000x reference)
#include <cuda_runtime.h>
#include <math.h>

// Problem shapes (fixed by setup_inputs): B=512, N=199, F=64, H=4, U=64
#define BB   512
#define NN   199
#define FF   64
#define HH   4
#define UU   64
#define MT   32                  // row tile for phase 2
#define COUT (HH*UU + NN)        // 455
#define NTHR 512

// Scratch: AW^T[h][m][n] = A[n][m] * params[h][n][m]  (634 KB, L2-resident)
__device__ float g_AWT[HH * NN * NN];

__global__ void awt_kernel(const float* __restrict__ A, const float* __restrict__ P) {
    int m = blockIdx.x, h = blockIdx.y;
    for (int n = threadIdx.x; n < NN; n += blockDim.x)
        g_AWT[((size_t)h * NN + m) * NN + n] = A[n * NN + m] * P[((size_t)h * NN + n) * NN + m];
}

// Fused per-(b,h) kernel. Shared layout (floats):
//  Xs [NN][FF]  X_b            (12736)
//  Fs [NN][FF]  feat           (12736)
//  Ks [FF][NN]  kernels_h      (12736)
//  fcS[FF][UU]  fc_h           (4096)
//  Dt [MT][200] AWT stage / dense / mask tile (6400)
//  Nd [MT][FF]  node tile      (2048)
// total 50752 floats = 203008 B
#define SMEM_FLOATS (NN*FF*3 + FF*UU + MT*200 + MT*FF)

__global__ __launch_bounds__(NTHR, 1)
void gc_kernel(const float* __restrict__ X, const float* __restrict__ A,
               const float* __restrict__ Kg, const float* __restrict__ FCg,
               const float* __restrict__ b1, const float* __restrict__ b2,
               float* __restrict__ out) {
    extern __shared__ float sm[];
    float* Xs  = sm;
    float* Fs  = Xs + NN * FF;
    float* Ks  = Fs + NN * FF;
    float* fcS = Ks + FF * NN;
    float* Dt  = fcS + FF * UU;
    float* Nd  = Dt + MT * 200;

    const int b = blockIdx.x, h = blockIdx.y;
    const int tid  = threadIdx.x;
    const int lane = tid & 31, wid = tid >> 5;
    const int f4 = tid & 15, mg = tid >> 4;   // 16 x 32 thread map for float4 GEMMs

    // ---- stage inputs ----
    float4* Xs4 = (float4*)Xs;
    const float4* Xg4 = (const float4*)(X + (size_t)b * NN * FF);
    for (int i = tid; i < NN * FF / 4; i += NTHR) Xs4[i] = Xg4[i];
    const float* kg = Kg + (size_t)h * FF * NN;
    for (int i = tid; i < FF * NN; i += NTHR) Ks[i] = kg[i];
    float4* fcS4 = (float4*)fcS;
    const float4* fg4 = (const float4*)(FCg + (size_t)h * FF * UU);
    for (int i = tid; i < FF * UU / 4; i += NTHR) fcS4[i] = fg4[i];
    __syncthreads();

    // ---- Phase 1: feat[m][f] = sum_n AWT[m][n] * X[n][f] ----
    const float* awt = g_AWT + (size_t)h * NN * NN;
    for (int m0 = 0; m0 < NN; m0 += MT) {
        int rows = min(MT, NN - m0);
        for (int i = tid; i < rows * NN; i += NTHR) Dt[i] = awt[(size_t)m0 * NN + i];
        __syncthreads();
        if (mg < rows) {
            const float* ar = Dt + mg * NN;
            float4 acc = make_float4(0.f, 0.f, 0.f, 0.f);
            #pragma unroll 4
            for (int n = 0; n < NN; ++n) {
                float aw = ar[n];
                float4 xv = Xs4[n * 16 + f4];
                acc.x = fmaf(aw, xv.x, acc.x);
                acc.y = fmaf(aw, xv.y, acc.y);
                acc.z = fmaf(aw, xv.z, acc.z);
                acc.w = fmaf(aw, xv.w, acc.w);
            }
            ((float4*)Fs)[(m0 + mg) * 16 + f4] = acc;
        }
        __syncthreads();
    }

    // ---- Phase 2: tiles of MT rows ----
    for (int m0 = 0; m0 < NN; m0 += MT) {
        int rows = min(MT, NN - m0);

        // 2a: dense rows (2 rows per warp, shared Ks loads) + 2b: masked softmax
        {
            int r0 = wid * 2;
            if (r0 < rows) {
                bool two = (r0 + 1 < rows);
                const float* f0 = Fs + (size_t)(m0 + r0) * FF;
                const float* f1 = Fs + (size_t)(m0 + (two ? r0 + 1 : r0)) * FF;
                float acc0[7], acc1[7];
                #pragma unroll
                for (int t = 0; t < 7; ++t) {
                    int j = lane + 32 * t;
                    float bv = (j < NN) ? b1[h * NN + j] : 0.f;
                    acc0[t] = bv; acc1[t] = bv;
                }
                for (int f = 0; f < FF; ++f) {
                    float a0 = f0[f], a1 = f1[f];
                    const float* kr = Ks + f * NN;
                    #pragma unroll
                    for (int t = 0; t < 7; ++t) {
                        int j = lane + 32 * t;
                        if (j < NN) {
                            float kv = kr[j];
                            acc0[t] = fmaf(a0, kv, acc0[t]);
                            acc1[t] = fmaf(a1, kv, acc1[t]);
                        }
                    }
                }
                #define DO_SOFTMAX(ACC, RIDX)                                              \
                {                                                                          \
                    int m = m0 + (RIDX);                                                   \
                    const float* Ar = A + (size_t)m * NN;                                  \
                    float vmax = -INFINITY;                                                \
                    _Pragma("unroll")                                                      \
                    for (int t = 0; t < 7; ++t) {                                          \
                        int j = lane + 32 * t;                                             \
                        if (j < NN) {                                                      \
                            if (Ar[j] == 0.f) ACC[t] -= 1e16f;                             \
                            vmax = fmaxf(vmax, ACC[t]);                                    \
                        }                                                                  \
                    }                                                                      \
                    for (int o = 16; o; o >>= 1)                                           \
                        vmax = fmaxf(vmax, __shfl_xor_sync(0xffffffffu, vmax, o));         \
                    float ssum = 0.f;                                                      \
                    _Pragma("unroll")                                                      \
                    for (int t = 0; t < 7; ++t) {                                          \
                        int j = lane + 32 * t;                                             \
                        if (j < NN) { ACC[t] = __expf(ACC[t] - vmax); ssum += ACC[t]; }    \
                    }                                                                      \
                    for (int o = 16; o; o >>= 1)                                           \
                        ssum += __shfl_xor_sync(0xffffffffu, ssum, o);                     \
                    float inv = 1.f / ssum;                                                \
                    float* drow = Dt + (size_t)(RIDX) * 200;                               \
                    float* mout = out + ((size_t)b * NN + m) * COUT + HH * UU;             \
                    _Pragma("unroll")                                                      \
                    for (int t = 0; t < 7; ++t) {                                          \
                        int j = lane + 32 * t;                                             \
                        if (j < NN) {                                                      \
                            float mv = ACC[t] * inv;                                       \
                            drow[j] = mv;                                                  \
                            if (h == HH - 1) mout[j] = mv;                                 \
                        }                                                                  \
                    }                                                                      \
                }
                DO_SOFTMAX(acc0, r0)
                if (two) DO_SOFTMAX(acc1, r0 + 1)
                #undef DO_SOFTMAX
            }
        }
        __syncthreads();

        // 2c: node[mi][f] = sum_j mask[mi][j] * X[j][f]
        if (mg < rows) {
            const float* mr = Dt + mg * 200;
            float4 acc = make_float4(0.f, 0.f, 0.f, 0.f);
            #pragma unroll 4
            for (int j = 0; j < NN; ++j) {
                float mv = mr[j];
                float4 xv = Xs4[j * 16 + f4];
                acc.x = fmaf(mv, xv.x, acc.x);
                acc.y = fmaf(mv, xv.y, acc.y);
                acc.z = fmaf(mv, xv.z, acc.z);
                acc.w = fmaf(mv, xv.w, acc.w);
            }
            ((float4*)Nd)[mg * 16 + f4] = acc;
        }
        __syncthreads();

        // 2d: out[mi][u] = sum_f node[mi][f] * fc[f][u] + b2[u]  (u strided for coalesced STG)
        if (mg < rows) {
            const float* nr = Nd + mg * FF;
            float a0 = b2[h * UU + f4];
            float a1 = b2[h * UU + f4 + 16];
            float a2 = b2[h * UU + f4 + 32];
            float a3 = b2[h * UU + f4 + 48];
            #pragma unroll 4
            for (int f = 0; f < FF; ++f) {
                float nv = nr[f];
                const float* fr = fcS + f * UU;
                a0 = fmaf(nv, fr[f4], a0);
                a1 = fmaf(nv, fr[f4 + 16], a1);
                a2 = fmaf(nv, fr[f4 + 32], a2);
                a3 = fmaf(nv, fr[f4 + 48], a3);
            }
            int m = m0 + mg;
            float* orow = out + ((size_t)b * NN + m) * COUT + (size_t)h * UU;
            orow[f4]      = a0;
            orow[f4 + 16] = a1;
            orow[f4 + 32] = a2;
            orow[f4 + 48] = a3;
        }
        __syncthreads();
    }
}

extern "C" void kernel_launch(void* const* d_in, const int* in_sizes, int n_in,
                              void* d_out, int out_size) {
    // Positional defaults per reference signature; remap defensively by element count
    // (all seven sizes are distinct for this problem).
    const float* X  = (const float*)d_in[0];
    const float* A  = (const float*)d_in[1];
    const float* Kg = (const float*)d_in[2];
    const float* P  = (const float*)d_in[3];
    const float* FC = (const float*)d_in[4];
    const float* b1 = (const float*)d_in[5];
    const float* b2 = (const float*)d_in[6];
    for (int i = 0; i < n_in; ++i) {
        int s = in_sizes[i];
        const float* p = (const float*)d_in[i];
        if      (s == BB * NN * FF) X  = p;
        else if (s == NN * NN)      A  = p;
        else if (s == HH * FF * NN) Kg = p;
        else if (s == HH * NN * NN) P  = p;
        else if (s == HH * FF * UU) FC = p;
        else if (s == HH * NN)      b1 = p;
        else if (s == HH * UU)      b2 = p;
    }

    awt_kernel<<<dim3(NN, HH), 128>>>(A, P);

    static int smem_set = 0;
    size_t smem = SMEM_FLOATS * sizeof(float);
    if (!smem_set) {
        cudaFuncSetAttribute(gc_kernel, cudaFuncAttributeMaxDynamicSharedMemorySize, (int)smem);
        smem_set = 1;
    }
    gc_kernel<<<dim3(BB, HH), NTHR, smem>>>(X, A, Kg, FC, b1, b2, (float*)d_out);
}

// round 3
// speedup vs baseline: 1.1124x; 1.1124x over previous
#include <cuda_runtime.h>
#include <math.h>

// Shapes fixed by setup_inputs: B=512, N=199, F=64, H=4, U=64
#define BB   512
#define NN   199
#define NP   200                 // padded K-dim stride (AWT cols, Xs rows)
#define FF   64
#define HH   4
#define UU   64
#define MT   64                  // phase-2 row tile
#define COUT (HH*UU + NN)        // 455
#define NTHR 512
#define FS_STRIDE 66             // feat/node row stride (conflict-free scalar row loads)
#define FS_FLOATS 13136          // NN*FS_STRIDE=13134 rounded up to mult of 4 (keeps Ks 16B-aligned)
#define KS_STRIDE 208            // kernels row stride (zero-padded, mult of 4)
#define DT_STRIDE 209            // dense/mask tile stride (odd -> conflict-free row loads)

typedef unsigned long long u64;

// AWT[h][m][n] = A[n][m] * params[h][n][m], col 199 zero-padded. 640KB, L2-resident.
__device__ float g_AWT[HH * NN * NP];

__global__ void awt_kernel(const float* __restrict__ A, const float* __restrict__ P) {
    int m = blockIdx.x, h = blockIdx.y;
    for (int n = threadIdx.x; n < NP; n += blockDim.x) {
        float v = 0.f;
        if (n < NN) v = A[n * NN + m] * P[((size_t)h * NN + n) * NN + m];
        g_AWT[((size_t)h * NN + m) * NP + n] = v;
    }
}

// ---- packed fp32x2 helpers (Blackwell FFMA2 path, PTX-only) ----
__device__ __forceinline__ void fma2(u64 &acc, u64 a, u64 b) {
    asm("fma.rn.f32x2 %0, %1, %2, %0;" : "+l"(acc) : "l"(a), "l"(b));
}
__device__ __forceinline__ u64 dup2(float v) {
    u64 r; unsigned u = __float_as_uint(v);
    asm("mov.b64 %0, {%1, %1};" : "=l"(r) : "r"(u));
    return r;
}
__device__ __forceinline__ u64 pack2(float a, float b) {
    u64 r; unsigned x = __float_as_uint(a), y = __float_as_uint(b);
    asm("mov.b64 %0, {%1, %2};" : "=l"(r) : "r"(x), "r"(y));
    return r;
}
__device__ __forceinline__ u64 add2(u64 a, u64 b) {
    u64 r; asm("add.rn.f32x2 %0, %1, %2;" : "=l"(r) : "l"(a), "l"(b));
    return r;
}
__device__ __forceinline__ float lo2(u64 a) {
    unsigned x, y; asm("mov.b64 {%0, %1}, %2;" : "=r"(x), "=r"(y) : "l"(a));
    return __uint_as_float(x);
}
__device__ __forceinline__ float hi2(u64 a) {
    unsigned x, y; asm("mov.b64 {%0, %1}, %2;" : "=r"(x), "=r"(y) : "l"(a));
    return __uint_as_float(y);
}

// SMEM (floats): Xs 12800 + Fs 13136 + Ks 13312 + fcS 4096 + Dt 13376 = 56720 -> 226880 B
// Alignment: Xs@0, Fs@12800 (16B ok), Ks@25936 (16B ok), fcS@39248 (16B ok), Dt@43344.
#define SMEM_FLOATS (NP*FF + FS_FLOATS + FF*KS_STRIDE + FF*UU + MT*DT_STRIDE)

__global__ __launch_bounds__(NTHR, 1)
void gc_kernel(const float* __restrict__ X, const float* __restrict__ A,
               const float* __restrict__ Kg, const float* __restrict__ FCg,
               const float* __restrict__ b1, const float* __restrict__ b2,
               float* __restrict__ out) {
    extern __shared__ float sm[];
    float* Xs  = sm;                       // [NP][FF]   X_b (row 199 zeroed)
    float* Fs  = Xs + NP * FF;             // [NN][66]   feat -> node (padded region)
    float* Ks  = Fs + FS_FLOATS;           // [FF][208]  kernels_h (zero-padded)
    float* fcS = Ks + FF * KS_STRIDE;      // [FF][UU]
    float* Dt  = fcS + FF * UU;            // [MT][209]  dense/mask tile

    const int b = blockIdx.x, h = blockIdx.y;
    const int tid  = threadIdx.x;
    const int lane = tid & 31, wid = tid >> 5;
    const int jf = lane & 7;               // 8-wide column group (cols jf*8 .. jf*8+7)
    const int rg = lane >> 3;              // 4 row sub-groups

    // ---- stage inputs ----
    {
        float4* Xs4 = (float4*)Xs;
        const float4* Xg4 = (const float4*)(X + (size_t)b * NN * FF);
        for (int i = tid; i < NN * FF / 4; i += NTHR) Xs4[i] = Xg4[i];
        if (tid < FF) Xs[NN * FF + tid] = 0.f;   // zero pad row 199
        const float* kg = Kg + (size_t)h * FF * NN;
        for (int i = tid; i < FF * KS_STRIDE; i += NTHR) {
            int f = i / KS_STRIDE, c = i - f * KS_STRIDE;
            Ks[i] = (c < NN) ? kg[f * NN + c] : 0.f;
        }
        float4* fcS4 = (float4*)fcS;
        const float4* fg4 = (const float4*)(FCg + (size_t)h * FF * UU);
        for (int i = tid; i < FF * UU / 4; i += NTHR) fcS4[i] = fg4[i];
    }
    __syncthreads();

    // ---- Phase 1: feat[m][f] = sum_n AWT[m][n] * X[n][f] ----
    // 13 warps x 16 rows; thread = 4 rows x 8 f; AWT streamed from L2 (float4/4n, prefetched)
    if (wid < 13) {
        const int rb = wid * 16 + rg * 4;
        const int r0c = min(rb + 0, NN - 1), r1c = min(rb + 1, NN - 1);
        const int r2c = min(rb + 2, NN - 1), r3c = min(rb + 3, NN - 1);
        const float4* aw0 = (const float4*)(g_AWT + ((size_t)h * NN + r0c) * NP);
        const float4* aw1 = (const float4*)(g_AWT + ((size_t)h * NN + r1c) * NP);
        const float4* aw2 = (const float4*)(g_AWT + ((size_t)h * NN + r2c) * NP);
        const float4* aw3 = (const float4*)(g_AWT + ((size_t)h * NN + r3c) * NP);

        u64 acc[4][4];
        #pragma unroll
        for (int r = 0; r < 4; ++r)
            #pragma unroll
            for (int k = 0; k < 4; ++k) acc[r][k] = 0ull;

        float4 c0 = aw0[0], c1 = aw1[0], c2 = aw2[0], c3 = aw3[0];
        #pragma unroll 1
        for (int n0 = 0; n0 < NP; n0 += 4) {
            float4 p0 = c0, p1 = c1, p2 = c2, p3 = c3;
            if (n0 + 4 < NP) {           // prefetch next block
                int nb = (n0 >> 2) + 1;
                p0 = aw0[nb]; p1 = aw1[nb]; p2 = aw2[nb]; p3 = aw3[nb];
            }
            #pragma unroll
            for (int nn = 0; nn < 4; ++nn) {
                const float* xb = Xs + (n0 + nn) * FF + jf * 8;
                ulonglong2 xa = *(const ulonglong2*)(xb);
                ulonglong2 xc = *(const ulonglong2*)(xb + 4);
                float a0 = nn == 0 ? c0.x : nn == 1 ? c0.y : nn == 2 ? c0.z : c0.w;
                float a1 = nn == 0 ? c1.x : nn == 1 ? c1.y : nn == 2 ? c1.z : c1.w;
                float a2 = nn == 0 ? c2.x : nn == 1 ? c2.y : nn == 2 ? c2.z : c2.w;
                float a3 = nn == 0 ? c3.x : nn == 1 ? c3.y : nn == 2 ? c3.z : c3.w;
                u64 d;
                d = dup2(a0); fma2(acc[0][0], d, xa.x); fma2(acc[0][1], d, xa.y);
                              fma2(acc[0][2], d, xc.x); fma2(acc[0][3], d, xc.y);
                d = dup2(a1); fma2(acc[1][0], d, xa.x); fma2(acc[1][1], d, xa.y);
                              fma2(acc[1][2], d, xc.x); fma2(acc[1][3], d, xc.y);
                d = dup2(a2); fma2(acc[2][0], d, xa.x); fma2(acc[2][1], d, xa.y);
                              fma2(acc[2][2], d, xc.x); fma2(acc[2][3], d, xc.y);
                d = dup2(a3); fma2(acc[3][0], d, xa.x); fma2(acc[3][1], d, xa.y);
                              fma2(acc[3][2], d, xc.x); fma2(acc[3][3], d, xc.y);
            }
            c0 = p0; c1 = p1; c2 = p2; c3 = p3;
        }
        #pragma unroll
        for (int r = 0; r < 4; ++r) {
            int row = rb + r;
            if (row < NN) {
                u64* fr = (u64*)(Fs + row * FS_STRIDE + jf * 8);
                fr[0] = acc[r][0]; fr[1] = acc[r][1]; fr[2] = acc[r][2]; fr[3] = acc[r][3];
            }
        }
    }
    __syncthreads();

    // ---- Phase 2: 64-row tiles ----
    for (int m0 = 0; m0 < NN; m0 += MT) {
        // 2a: dense[m][j] = sum_f feat[m][f]*K[f][j] + b1[j]
        // 16 warps = wr(4 row groups of 16) x wj(4 j-tiles of 64); thread = 4 rows x 8 j
        {
            const int wj = wid & 3, wr = wid >> 2;
            const int cb = wj * 64 + jf * 8;
            const int cl = (cb <= 200) ? cb : 192;   // clamped, in-bounds Ks col base
            const int rb = m0 + wr * 16 + rg * 4;
            const float* f0p = Fs + min(rb + 0, NN - 1) * FS_STRIDE;
            const float* f1p = Fs + min(rb + 1, NN - 1) * FS_STRIDE;
            const float* f2p = Fs + min(rb + 2, NN - 1) * FS_STRIDE;
            const float* f3p = Fs + min(rb + 3, NN - 1) * FS_STRIDE;

            u64 bini[4];
            #pragma unroll
            for (int k = 0; k < 4; ++k) {
                int j0 = cb + k * 2;
                float v0 = (j0     < NN) ? b1[h * NN + j0]     : 0.f;
                float v1 = (j0 + 1 < NN) ? b1[h * NN + j0 + 1] : 0.f;
                bini[k] = pack2(v0, v1);
            }
            u64 acc[4][4];
            #pragma unroll
            for (int r = 0; r < 4; ++r)
                #pragma unroll
                for (int k = 0; k < 4; ++k) acc[r][k] = bini[k];

            #pragma unroll 2
            for (int f = 0; f < FF; ++f) {
                const float* kb = Ks + f * KS_STRIDE + cl;
                ulonglong2 ka = *(const ulonglong2*)(kb);
                ulonglong2 kc = *(const ulonglong2*)(kb + 4);
                u64 d;
                d = dup2(f0p[f]); fma2(acc[0][0], d, ka.x); fma2(acc[0][1], d, ka.y);
                                  fma2(acc[0][2], d, kc.x); fma2(acc[0][3], d, kc.y);
                d = dup2(f1p[f]); fma2(acc[1][0], d, ka.x); fma2(acc[1][1], d, ka.y);
                                  fma2(acc[1][2], d, kc.x); fma2(acc[1][3], d, kc.y);
                d = dup2(f2p[f]); fma2(acc[2][0], d, ka.x); fma2(acc[2][1], d, ka.y);
                                  fma2(acc[2][2], d, kc.x); fma2(acc[2][3], d, kc.y);
                d = dup2(f3p[f]); fma2(acc[3][0], d, ka.x); fma2(acc[3][1], d, ka.y);
                                  fma2(acc[3][2], d, kc.x); fma2(acc[3][3], d, kc.y);
            }
            #pragma unroll
            for (int r = 0; r < 4; ++r) {
                float* dr = Dt + (wr * 16 + rg * 4 + r) * DT_STRIDE;
                #pragma unroll
                for (int k = 0; k < 4; ++k) {
                    int j0 = cb + k * 2;
                    if (j0     < NN) dr[j0]     = lo2(acc[r][k]);
                    if (j0 + 1 < NN) dr[j0 + 1] = hi2(acc[r][k]);
                }
            }
        }
        __syncthreads();

        // 2b: adjacency-masked softmax per row; warp handles 4 rows
        #pragma unroll
        for (int rr = 0; rr < 4; ++rr) {
            int rl = wid * 4 + rr;
            int m  = m0 + rl;
            if (m < NN) {
                const float* Ar = A + (size_t)m * NN;
                float* dr = Dt + rl * DT_STRIDE;
                float v[7];
                float vmax = -INFINITY;
                #pragma unroll
                for (int t = 0; t < 7; ++t) {
                    int j = lane + 32 * t;
                    if (j < NN) {
                        float x = dr[j];
                        if (Ar[j] == 0.f) x -= 1e16f;
                        v[t] = x; vmax = fmaxf(vmax, x);
                    } else v[t] = -INFINITY;
                }
                for (int o = 16; o; o >>= 1) vmax = fmaxf(vmax, __shfl_xor_sync(0xffffffffu, vmax, o));
                float s = 0.f;
                #pragma unroll
                for (int t = 0; t < 7; ++t) {
                    int j = lane + 32 * t;
                    if (j < NN) { v[t] = __expf(v[t] - vmax); s += v[t]; }
                }
                for (int o = 16; o; o >>= 1) s += __shfl_xor_sync(0xffffffffu, s, o);
                float inv = 1.f / s;
                float* mout = out + ((size_t)b * NN + m) * COUT + HH * UU;
                #pragma unroll
                for (int t = 0; t < 7; ++t) {
                    int j = lane + 32 * t;
                    if (j < NN) {
                        float mv = v[t] * inv;
                        dr[j] = mv;
                        if (h == HH - 1) mout[j] = mv;
                    }
                }
            }
        }
        __syncthreads();

        // 2c: node[m][f] = sum_j mask[m][j]*X[j][f]
        // 16 warps = rgrp(4 row groups of 16) x jsp(4-way K split); thread = 4 rows x 8 f
        {
            const int jsp = wid >> 2, rgrp = wid & 3;
            const int j0 = jsp * 50, j1 = min(NN, j0 + 50);
            const int rlb = rgrp * 16 + rg * 4;
            const float* d0 = Dt + (rlb + 0) * DT_STRIDE;
            const float* d1 = Dt + (rlb + 1) * DT_STRIDE;
            const float* d2 = Dt + (rlb + 2) * DT_STRIDE;
            const float* d3 = Dt + (rlb + 3) * DT_STRIDE;

            u64 acc[4][4];
            #pragma unroll
            for (int r = 0; r < 4; ++r)
                #pragma unroll
                for (int k = 0; k < 4; ++k) acc[r][k] = 0ull;

            #pragma unroll 2
            for (int j = j0; j < j1; ++j) {
                const float* xb = Xs + j * FF + jf * 8;
                ulonglong2 xa = *(const ulonglong2*)(xb);
                ulonglong2 xc = *(const ulonglong2*)(xb + 4);
                u64 d;
                d = dup2(d0[j]); fma2(acc[0][0], d, xa.x); fma2(acc[0][1], d, xa.y);
                                 fma2(acc[0][2], d, xc.x); fma2(acc[0][3], d, xc.y);
                d = dup2(d1[j]); fma2(acc[1][0], d, xa.x); fma2(acc[1][1], d, xa.y);
                                 fma2(acc[1][2], d, xc.x); fma2(acc[1][3], d, xc.y);
                d = dup2(d2[j]); fma2(acc[2][0], d, xa.x); fma2(acc[2][1], d, xa.y);
                                 fma2(acc[2][2], d, xc.x); fma2(acc[2][3], d, xc.y);
                d = dup2(d3[j]); fma2(acc[3][0], d, xa.x); fma2(acc[3][1], d, xa.y);
                                 fma2(acc[3][2], d, xc.x); fma2(acc[3][3], d, xc.y);
            }
            // 4-round K-split reduction into Fs (node overwrites dead feat rows)
            for (int round = 0; round < 4; ++round) {
                if (jsp == round) {
                    #pragma unroll
                    for (int r = 0; r < 4; ++r) {
                        int row = m0 + rlb + r;
                        if (row < NN) {
                            u64* fr = (u64*)(Fs + row * FS_STRIDE + jf * 8);
                            if (round == 0) {
                                fr[0] = acc[r][0]; fr[1] = acc[r][1];
                                fr[2] = acc[r][2]; fr[3] = acc[r][3];
                            } else {
                                fr[0] = add2(fr[0], acc[r][0]); fr[1] = add2(fr[1], acc[r][1]);
                                fr[2] = add2(fr[2], acc[r][2]); fr[3] = add2(fr[3], acc[r][3]);
                            }
                        }
                    }
                }
                __syncthreads();
            }
        }

        // 2d: out[m][u] = sum_f node[m][f]*fc[f][u] + b2[u]; thread = 1 row x 8 u
        {
            int row = m0 + wid * 4 + rg;
            if (row < NN) {
                u64 acc4[4];
                #pragma unroll
                for (int k = 0; k < 4; ++k) {
                    int u0 = jf * 8 + k * 2;
                    acc4[k] = pack2(b2[h * UU + u0], b2[h * UU + u0 + 1]);
                }
                const float* nr = Fs + row * FS_STRIDE;
                #pragma unroll 2
                for (int f = 0; f < FF; ++f) {
                    const float* cb_ = fcS + f * UU + jf * 8;
                    ulonglong2 ca = *(const ulonglong2*)(cb_);
                    ulonglong2 cc = *(const ulonglong2*)(cb_ + 4);
                    u64 d = dup2(nr[f]);
                    fma2(acc4[0], d, ca.x); fma2(acc4[1], d, ca.y);
                    fma2(acc4[2], d, cc.x); fma2(acc4[3], d, cc.y);
                }
                float* orow = out + ((size_t)b * NN + row) * COUT + h * UU + jf * 8;
                orow[0] = lo2(acc4[0]); orow[1] = hi2(acc4[0]);
                orow[2] = lo2(acc4[1]); orow[3] = hi2(acc4[1]);
                orow[4] = lo2(acc4[2]); orow[5] = hi2(acc4[2]);
                orow[6] = lo2(acc4[3]); orow[7] = hi2(acc4[3]);
            }
        }
        __syncthreads();
    }
}

extern "C" void kernel_launch(void* const* d_in, const int* in_sizes, int n_in,
                              void* d_out, int out_size) {
    const float* X  = (const float*)d_in[0];
    const float* A  = (const float*)d_in[1];
    const float* Kg = (const float*)d_in[2];
    const float* P  = (const float*)d_in[3];
    const float* FC = (const float*)d_in[4];
    const float* b1 = (const float*)d_in[5];
    const float* b2 = (const float*)d_in[6];
    for (int i = 0; i < n_in; ++i) {   // defensive remap: all sizes distinct
        int s = in_sizes[i];
        const float* p = (const float*)d_in[i];
        if      (s == BB * NN * FF) X  = p;
        else if (s == NN * NN)      A  = p;
        else if (s == HH * FF * NN) Kg = p;
        else if (s == HH * NN * NN) P  = p;
        else if (s == HH * FF * UU) FC = p;
        else if (s == HH * NN)      b1 = p;
        else if (s == HH * UU)      b2 = p;
    }

    awt_kernel<<<dim3(NN, HH), 128>>>(A, P);

    static int smem_set = 0;
    size_t smem = SMEM_FLOATS * sizeof(float);
    if (!smem_set) {
        cudaFuncSetAttribute(gc_kernel, cudaFuncAttributeMaxDynamicSharedMemorySize, (int)smem);
        smem_set = 1;
    }
    gc_kernel<<<dim3(BB, HH), NTHR, smem>>>(X, A, Kg, FC, b1, b2, (float*)d_out);
}